// round 12
// baseline (speedup 1.0000x reference)
#include <cuda_runtime.h>

// QConv1d, conjugation closed form; f32x2 lanes hold the CO-PAIR (R11 base).
// Change: invariants computed PACKED from loop-invariant packed v broadcasts,
// cutting per-tap broadcasts from 10 to 4.
// x: (B, CIN, T, 4)   a,b,c: (COUT, CIN, FL)   out: (B, COUT, TOUT, 4)

#define B_    2
#define CIN_  16
#define COUT_ 16
#define T_    2048
#define FL_   9
#define TOUT_ 2040
#define NQ    2        // co per thread (packed in f32x2 halves)

typedef unsigned long long ull;

__device__ __forceinline__ ull pk2(float lo, float hi) {
    ull r; asm("mov.b64 %0,{%1,%2};" : "=l"(r)
               : "r"(__float_as_uint(lo)), "r"(__float_as_uint(hi)));
    return r;
}
__device__ __forceinline__ void upk2(ull v, float& lo, float& hi) {
    unsigned a, b; asm("mov.b64 {%0,%1},%2;" : "=r"(a), "=r"(b) : "l"(v));
    lo = __uint_as_float(a); hi = __uint_as_float(b);
}
__device__ __forceinline__ ull bc2(float v) { return pk2(v, v); }
__device__ __forceinline__ ull f2(ull a, ull b, ull c) {
    ull r; asm("fma.rn.f32x2 %0,%1,%2,%3;" : "=l"(r) : "l"(a), "l"(b), "l"(c));
    return r;
}
__device__ __forceinline__ ull m2(ull a, ull b) {
    ull r; asm("mul.rn.f32x2 %0,%1,%2;" : "=l"(r) : "l"(a), "l"(b));
    return r;
}
__device__ __forceinline__ ull a2_(ull a, ull b) {
    ull r; asm("add.rn.f32x2 %0,%1,%2;" : "=l"(r) : "l"(a), "l"(b));
    return r;
}
__device__ __forceinline__ float rcpf(float x) {
    float r; asm("rcp.approx.f32 %0,%1;" : "=f"(r) : "f"(x));
    return r;
}

__global__ __launch_bounds__(32 * CIN_)
void qconv1d_kernel(const float* __restrict__ x,
                    const float* __restrict__ pa,
                    const float* __restrict__ pb,
                    const float* __restrict__ pc,
                    float* __restrict__ out)
{
    __shared__ ull sp[CIN_][FL_][3];            // packed {a,b,c} over the co-pair
    __shared__ ull red[CIN_ - 1][32][4];        // packed accumulators

    const int tx  = threadIdx.x;
    const int ci  = threadIdx.y;
    const int tid = ci * 32 + tx;
    const int t   = blockIdx.x * 32 + tx;
    const int co0 = blockIdx.y * NQ;
    const int b   = blockIdx.z;
    const int tL  = t < TOUT_ ? t : (TOUT_ - 1);

    // pack params over the co-pair: 144 entries, 512 threads
    if (tid < CIN_ * FL_) {
        const int cci = tid / FL_, f = tid % FL_;
        const int s0 = (co0 * CIN_ + cci) * FL_ + f;
        const int s1 = s0 + CIN_ * FL_;
        sp[cci][f][0] = pk2(__ldg(pa + s0), __ldg(pa + s1));
        sp[cci][f][1] = pk2(__ldg(pb + s0), __ldg(pb + s1));
        sp[cci][f][2] = pk2(__ldg(pc + s0), __ldg(pc + s1));
    }
    __syncthreads();

    const float4* xr = reinterpret_cast<const float4*>(x)
                     + ((size_t)b * CIN_ + ci) * T_ + tL;

    // center tap qp: all v-derived packed constants made ONCE (loop-invariant)
    const float4 v4 = __ldg(xr + 4);
    const float vx = v4.y, vy = v4.z, vz = v4.w;
    const float vsq = vx * vx + vy * vy + vz * vz;
    const ull pw2   = bc2(v4.x);
    const ull vsq2  = bc2(vsq);
    const ull nvsq2 = bc2(-vsq);
    const ull vx2   = bc2(vx);
    const ull vy2   = bc2(vy);
    const ull vz2   = bc2(vz);
    const ull vdx2  = bc2(vx + vx);
    const ull vdy2  = bc2(vy + vy);
    const ull vdz2  = bc2(vz + vz);
    const ull nvdx2 = bc2(-(vx + vx));
    const ull nvdy2 = bc2(-(vy + vy));
    const ull nvdz2 = bc2(-(vz + vz));
    const ull NEG1  = bc2(-1.0f);

    ull aw = 0, ax = 0, ay = 0, az = 0;

    #pragma unroll
    for (int f = 0; f < FL_; ++f) {
        const float4 u4 = __ldg(xr + f);
        // only 4 broadcasts per tap
        const ull s2  = bc2(u4.x);
        const ull ux2 = bc2(u4.y);
        const ull uy2 = bc2(u4.z);
        const ull uz2 = bc2(u4.w);

        // packed invariants: R(w) = w^2 u + w*(2 v x u) + (2(v.u) v - vsq u)
        const ull dp   = f2(vx2, ux2, f2(vy2, uy2, m2(vz2, uz2)));   // v.u
        const ull crx2 = f2(vdy2, uz2, m2(nvdz2, uy2));              // 2(v x u)
        const ull cry2 = f2(vdz2, ux2, m2(nvdx2, uz2));
        const ull crz2 = f2(vdx2, uy2, m2(nvdy2, ux2));
        const ull a0x2 = f2(dp, vdx2, m2(nvsq2, ux2));               // 2d v - vsq u
        const ull a0y2 = f2(dp, vdy2, m2(nvsq2, uy2));
        const ull a0z2 = f2(dp, vdz2, m2(nvsq2, uz2));

        // packed per-co body (both co at once)
        const ull A2 = sp[ci][f][0];
        const ull B2 = sp[ci][f][1];
        const ull C2 = sp[ci][f][2];

        const ull w2   = a2_(pw2, C2);
        const ull nsq2 = f2(w2, w2, vsq2);
        float nlo, nhi; upk2(nsq2, nlo, nhi);
        const ull rn2  = pk2(rcpf(nlo), rcpf(nhi));
        const ull arn2 = m2(A2, rn2);

        const ull Rx = m2(f2(w2, f2(w2, ux2, crx2), a0x2), arn2);
        const ull Ry = m2(f2(w2, f2(w2, uy2, cry2), a0y2), arn2);
        const ull Rz = m2(f2(w2, f2(w2, uz2, crz2), a0z2), arn2);
        const ull Rw = m2(s2, A2);
        const ull nRx = m2(Rx, NEG1);
        const ull nRy = m2(Ry, NEG1);
        const ull nRz = m2(Rz, NEG1);
        const ull qw2 = a2_(s2, B2);

        // acc += (q + b e) (x) R
        aw = f2(qw2, Rw, aw);
        aw = f2(ux2, nRx, aw);
        aw = f2(uy2, nRy, aw);
        aw = f2(uz2, nRz, aw);
        ax = f2(qw2, Rx, ax);
        ax = f2(ux2, Rw, ax);
        ax = f2(uy2, Rz, ax);
        ax = f2(uz2, nRy, ax);
        ay = f2(qw2, Ry, ay);
        ay = f2(ux2, nRz, ay);
        ay = f2(uy2, Rw, ay);
        ay = f2(uz2, Rx, ay);
        az = f2(qw2, Rz, az);
        az = f2(ux2, Ry, az);
        az = f2(uy2, nRx, az);
        az = f2(uz2, Rw, az);
    }

    // flat reduction over 16 ci warps (packed adds)
    if (ci > 0) {
        red[ci - 1][tx][0] = aw;
        red[ci - 1][tx][1] = ax;
        red[ci - 1][tx][2] = ay;
        red[ci - 1][tx][3] = az;
    }
    __syncthreads();
    if (ci == 0 && t < TOUT_) {
        #pragma unroll
        for (int k = 0; k < CIN_ - 1; ++k) {
            aw = a2_(aw, red[k][tx][0]);
            ax = a2_(ax, red[k][tx][1]);
            ay = a2_(ay, red[k][tx][2]);
            az = a2_(az, red[k][tx][3]);
        }
        float w0, w1, x0, x1, y0, y1, z0, z1;
        upk2(aw, w0, w1); upk2(ax, x0, x1); upk2(ay, y0, y1); upk2(az, z0, z1);
        float4* o4 = reinterpret_cast<float4*>(out) + (size_t)b * COUT_ * TOUT_ + t;
        o4[(size_t)(co0 + 0) * TOUT_] = make_float4(w0, x0, y0, z0);
        o4[(size_t)(co0 + 1) * TOUT_] = make_float4(w1, x1, y1, z1);
    }
}

extern "C" void kernel_launch(void* const* d_in, const int* in_sizes, int n_in,
                              void* d_out, int out_size)
{
    const float* x  = (const float*)d_in[0];
    const float* pa = (const float*)d_in[1];
    const float* pb = (const float*)d_in[2];
    const float* pc = (const float*)d_in[3];
    float* out = (float*)d_out;

    dim3 block(32, CIN_, 1);
    dim3 grid((TOUT_ + 31) / 32, COUT_ / NQ, B_);
    qconv1d_kernel<<<grid, block>>>(x, pa, pb, pc, out);
}

// round 13
// speedup vs baseline: 1.2256x; 1.2256x over previous
#include <cuda_runtime.h>

// QConv1d, conjugation closed form; f32x2 lanes hold the CO-PAIR (R11 base).
// Cuts: sign-split accumulators (no nR negations) + fused {a,b} LDS.128.
// x: (B, CIN, T, 4)   a,b,c: (COUT, CIN, FL)   out: (B, COUT, TOUT, 4)

#define B_    2
#define CIN_  16
#define COUT_ 16
#define T_    2048
#define FL_   9
#define TOUT_ 2040
#define NQ    2        // co per thread (packed in f32x2 halves)

typedef unsigned long long ull;

struct __align__(16) ull2x { ull a, b; };

__device__ __forceinline__ ull pk2(float lo, float hi) {
    ull r; asm("mov.b64 %0,{%1,%2};" : "=l"(r)
               : "r"(__float_as_uint(lo)), "r"(__float_as_uint(hi)));
    return r;
}
__device__ __forceinline__ void upk2(ull v, float& lo, float& hi) {
    unsigned a, b; asm("mov.b64 {%0,%1},%2;" : "=r"(a), "=r"(b) : "l"(v));
    lo = __uint_as_float(a); hi = __uint_as_float(b);
}
__device__ __forceinline__ ull bc2(float v) { return pk2(v, v); }
__device__ __forceinline__ ull f2(ull a, ull b, ull c) {
    ull r; asm("fma.rn.f32x2 %0,%1,%2,%3;" : "=l"(r) : "l"(a), "l"(b), "l"(c));
    return r;
}
__device__ __forceinline__ ull m2(ull a, ull b) {
    ull r; asm("mul.rn.f32x2 %0,%1,%2;" : "=l"(r) : "l"(a), "l"(b));
    return r;
}
__device__ __forceinline__ ull a2_(ull a, ull b) {
    ull r; asm("add.rn.f32x2 %0,%1,%2;" : "=l"(r) : "l"(a), "l"(b));
    return r;
}
__device__ __forceinline__ float rcpf(float x) {
    float r; asm("rcp.approx.f32 %0,%1;" : "=f"(r) : "f"(x));
    return r;
}

__global__ __launch_bounds__(32 * CIN_)
void qconv1d_kernel(const float* __restrict__ x,
                    const float* __restrict__ pa,
                    const float* __restrict__ pb,
                    const float* __restrict__ pc,
                    float* __restrict__ out)
{
    __shared__ ull2x spAB[CIN_][FL_];           // packed {a,b} over the co-pair
    __shared__ ull   spC[CIN_][FL_];            // packed {c}
    __shared__ ull   red[CIN_ - 1][32][4];

    const int tx  = threadIdx.x;
    const int ci  = threadIdx.y;
    const int tid = ci * 32 + tx;
    const int t   = blockIdx.x * 32 + tx;
    const int co0 = blockIdx.y * NQ;
    const int b   = blockIdx.z;
    const int tL  = t < TOUT_ ? t : (TOUT_ - 1);

    // pack params over the co-pair: 144 entries, 512 threads
    if (tid < CIN_ * FL_) {
        const int cci = tid / FL_, f = tid % FL_;
        const int s0 = (co0 * CIN_ + cci) * FL_ + f;
        const int s1 = s0 + CIN_ * FL_;
        ull2x ab;
        ab.a = pk2(__ldg(pa + s0), __ldg(pa + s1));
        ab.b = pk2(__ldg(pb + s0), __ldg(pb + s1));
        spAB[cci][f] = ab;
        spC[cci][f]  = pk2(__ldg(pc + s0), __ldg(pc + s1));
    }
    __syncthreads();

    const float4* xr = reinterpret_cast<const float4*>(x)
                     + ((size_t)b * CIN_ + ci) * T_ + tL;

    // center tap qp — scalar; one-time doubled copies
    const float4 v4 = __ldg(xr + 4);
    const float pw = v4.x, vx = v4.y, vy = v4.z, vz = v4.w;
    const float vdx = vx + vx, vdy = vy + vy, vdz = vz + vz;   // 2v
    const float vsq  = vx * vx + vy * vy + vz * vz;
    const float nvsq = -vsq;
    const ull pw2  = bc2(pw);
    const ull vsq2 = bc2(vsq);

    // positive accumulators + sign-split negative accumulators
    ull aw = 0, ax = 0, ay = 0, az = 0;
    ull Sn = 0, nx = 0, ny = 0, nz = 0;

    #pragma unroll
    for (int f = 0; f < FL_; ++f) {
        const float4 u4 = __ldg(xr + f);
        const float s = u4.x, ux = u4.y, uy = u4.z, uz = u4.w;

        // scalar co-invariants (pre-doubled): R(w) = w^2 u + w*cr + (dd v - vsq u)
        const float dd  = vdx*ux + vdy*uy + vdz*uz;            // 2 v.u
        const float crx = vdy*uz - vdz*uy;                     // 2 (v x u)
        const float cry = vdz*ux - vdx*uz;
        const float crz = vdx*uy - vdy*ux;
        const float a0x = fmaf(dd, vx, nvsq * ux);
        const float a0y = fmaf(dd, vy, nvsq * uy);
        const float a0z = fmaf(dd, vz, nvsq * uz);

        // broadcast to packed lanes (once per f, shared by both co)
        const ull s2   = bc2(s);
        const ull ux2  = bc2(ux);
        const ull uy2  = bc2(uy);
        const ull uz2  = bc2(uz);
        const ull crx2 = bc2(crx);
        const ull cry2 = bc2(cry);
        const ull crz2 = bc2(crz);
        const ull a0x2 = bc2(a0x);
        const ull a0y2 = bc2(a0y);
        const ull a0z2 = bc2(a0z);

        // packed per-co body (both co at once)
        const ull2x AB = spAB[ci][f];
        const ull C2 = spC[ci][f];

        const ull w2   = a2_(pw2, C2);
        const ull nsq2 = f2(w2, w2, vsq2);
        float nlo, nhi; upk2(nsq2, nlo, nhi);
        const ull rn2  = pk2(rcpf(nlo), rcpf(nhi));
        const ull arn2 = m2(AB.a, rn2);

        const ull Rx = m2(f2(w2, f2(w2, ux2, crx2), a0x2), arn2);
        const ull Ry = m2(f2(w2, f2(w2, uy2, cry2), a0y2), arn2);
        const ull Rz = m2(f2(w2, f2(w2, uz2, crz2), a0z2), arn2);
        const ull Rw = m2(s2, AB.a);
        const ull qw2 = a2_(s2, AB.b);

        // acc += (q + b e) (x) R  — negatives collected separately
        aw = f2(qw2, Rw, aw);
        Sn = f2(ux2, Rx, Sn);
        Sn = f2(uy2, Ry, Sn);
        Sn = f2(uz2, Rz, Sn);
        ax = f2(qw2, Rx, ax);
        ax = f2(ux2, Rw, ax);
        ax = f2(uy2, Rz, ax);
        nx = f2(uz2, Ry, nx);
        ay = f2(qw2, Ry, ay);
        ny = f2(ux2, Rz, ny);
        ay = f2(uy2, Rw, ay);
        ay = f2(uz2, Rx, ay);
        az = f2(qw2, Rz, az);
        az = f2(ux2, Ry, az);
        nz = f2(uy2, Rx, nz);
        az = f2(uz2, Rw, az);
    }

    // fold negatives once
    {
        const ull NEG1 = bc2(-1.0f);
        aw = f2(Sn, NEG1, aw);
        ax = f2(nx, NEG1, ax);
        ay = f2(ny, NEG1, ay);
        az = f2(nz, NEG1, az);
    }

    // flat reduction over 16 ci warps (packed adds)
    if (ci > 0) {
        red[ci - 1][tx][0] = aw;
        red[ci - 1][tx][1] = ax;
        red[ci - 1][tx][2] = ay;
        red[ci - 1][tx][3] = az;
    }
    __syncthreads();
    if (ci == 0 && t < TOUT_) {
        #pragma unroll
        for (int k = 0; k < CIN_ - 1; ++k) {
            aw = a2_(aw, red[k][tx][0]);
            ax = a2_(ax, red[k][tx][1]);
            ay = a2_(ay, red[k][tx][2]);
            az = a2_(az, red[k][tx][3]);
        }
        float w0, w1, x0, x1, y0, y1, z0, z1;
        upk2(aw, w0, w1); upk2(ax, x0, x1); upk2(ay, y0, y1); upk2(az, z0, z1);
        float4* o4 = reinterpret_cast<float4*>(out) + (size_t)b * COUT_ * TOUT_ + t;
        o4[(size_t)(co0 + 0) * TOUT_] = make_float4(w0, x0, y0, z0);
        o4[(size_t)(co0 + 1) * TOUT_] = make_float4(w1, x1, y1, z1);
    }
}

extern "C" void kernel_launch(void* const* d_in, const int* in_sizes, int n_in,
                              void* d_out, int out_size)
{
    const float* x  = (const float*)d_in[0];
    const float* pa = (const float*)d_in[1];
    const float* pb = (const float*)d_in[2];
    const float* pc = (const float*)d_in[3];
    float* out = (float*)d_out;

    dim3 block(32, CIN_, 1);
    dim3 grid((TOUT_ + 31) / 32, COUT_ / NQ, B_);
    qconv1d_kernel<<<grid, block>>>(x, pa, pb, pc, out);
}